// round 2
// baseline (speedup 1.0000x reference)
#include <cuda_runtime.h>
#include <math.h>

// Problem constants
#define D_   2048
#define S_   2048
#define B_   2
#define H_   16
#define DK_  128
#define BS_  (B_*S_)   // 4096 tokens
#define BH_  (B_*H_)   // 32 head-batches

// ---------------------------------------------------------------------------
// Device scratch (no allocations allowed)
// ---------------------------------------------------------------------------
__device__ float g_effw_q[D_*D_];
__device__ float g_effw_k[D_*D_];
__device__ float g_effw_v[D_*D_];
__device__ float g_effw_o[D_*D_];
__device__ float g_q[BH_*S_*DK_];
__device__ float g_k[BH_*S_*DK_];
__device__ float g_v[BH_*S_*DK_];
__device__ float g_ao[BS_*D_];

// ---------------------------------------------------------------------------
// effw = w + la @ lb   (la: [D, 8], lb: [8, D])
// ---------------------------------------------------------------------------
__global__ void effw_kernel(const float* __restrict__ w,
                            const float* __restrict__ la,
                            const float* __restrict__ lb,
                            float* __restrict__ out)
{
    int idx = blockIdx.x * 256 + threadIdx.x;     // 0 .. D*D-1
    int n = idx & (D_ - 1);
    int k = idx >> 11;
    float acc = w[idx];
#pragma unroll
    for (int r = 0; r < 8; r++)
        acc += la[k * 8 + r] * lb[r * D_ + n];
    out[idx] = acc;
}

// ---------------------------------------------------------------------------
// SGEMM: C[M=4096][N=2048] = A[4096][2048] @ W[2048][2048] + bias
// epi == 0: plain row-major store
// epi == 1: scatter to [B, H, S, dk] head-major layout
// Tile 128x128x16, 256 threads, 8x8 per thread, double-buffered smem.
// ---------------------------------------------------------------------------
__global__ __launch_bounds__(256) void sgemm_bias(
    const float* __restrict__ A, const float* __restrict__ W,
    const float* __restrict__ bias, float* __restrict__ C, int epi)
{
    __shared__ float As[2][16][132];   // A stored transposed: As[k][m]
    __shared__ float Ws[2][16][128];   // W stored natural:   Ws[k][n]

    const int tid = threadIdx.x;
    const int tx = tid & 15, ty = tid >> 4;
    const int bm = blockIdx.y << 7;
    const int bn = blockIdx.x << 7;

    // Load mapping
    const int arow = tid >> 2;          // 0..63  (second half at +64)
    const int acol = (tid & 3) << 2;    // 0,4,8,12
    const int wrow = tid >> 5;          // 0..7   (second half at +8)
    const int wcol = (tid & 31) << 2;   // 0..124

    const float* Abase = A + (bm + arow) * D_ + acol;
    const float* Wbase = W + wrow * D_ + bn + wcol;

    float acc[8][8];
#pragma unroll
    for (int i = 0; i < 8; i++)
#pragma unroll
        for (int j = 0; j < 8; j++) acc[i][j] = 0.f;

    // Prologue: load k-tile 0 into buffer 0
    float4 a0 = *(const float4*)(Abase);
    float4 a1 = *(const float4*)(Abase + 64 * D_);
    float4 w0 = *(const float4*)(Wbase);
    float4 w1 = *(const float4*)(Wbase + 8 * D_);
    As[0][acol + 0][arow] = a0.x;  As[0][acol + 1][arow] = a0.y;
    As[0][acol + 2][arow] = a0.z;  As[0][acol + 3][arow] = a0.w;
    As[0][acol + 0][arow + 64] = a1.x;  As[0][acol + 1][arow + 64] = a1.y;
    As[0][acol + 2][arow + 64] = a1.z;  As[0][acol + 3][arow + 64] = a1.w;
    *(float4*)&Ws[0][wrow][wcol]     = w0;
    *(float4*)&Ws[0][wrow + 8][wcol] = w1;
    __syncthreads();

    int buf = 0;
#pragma unroll 1
    for (int kt = 0; kt < 128; kt++) {
        const bool has = (kt < 127);
        if (has) {
            const float* Ak = Abase + (kt + 1) * 16;
            a0 = *(const float4*)(Ak);
            a1 = *(const float4*)(Ak + 64 * D_);
            const float* Wk = Wbase + (kt + 1) * 16 * D_;
            w0 = *(const float4*)(Wk);
            w1 = *(const float4*)(Wk + 8 * D_);
        }
        // Compute on current buffer
#pragma unroll
        for (int k = 0; k < 16; k++) {
            float4 x0 = *(const float4*)&As[buf][k][4 * ty];
            float4 x1 = *(const float4*)&As[buf][k][64 + 4 * ty];
            float4 y0 = *(const float4*)&Ws[buf][k][4 * tx];
            float4 y1 = *(const float4*)&Ws[buf][k][64 + 4 * tx];
            float xa[8] = {x0.x, x0.y, x0.z, x0.w, x1.x, x1.y, x1.z, x1.w};
            float yb[8] = {y0.x, y0.y, y0.z, y0.w, y1.x, y1.y, y1.z, y1.w};
#pragma unroll
            for (int i = 0; i < 8; i++)
#pragma unroll
                for (int j = 0; j < 8; j++)
                    acc[i][j] += xa[i] * yb[j];
        }
        if (has) {
            int nb = buf ^ 1;
            As[nb][acol + 0][arow] = a0.x;  As[nb][acol + 1][arow] = a0.y;
            As[nb][acol + 2][arow] = a0.z;  As[nb][acol + 3][arow] = a0.w;
            As[nb][acol + 0][arow + 64] = a1.x;  As[nb][acol + 1][arow + 64] = a1.y;
            As[nb][acol + 2][arow + 64] = a1.z;  As[nb][acol + 3][arow + 64] = a1.w;
            *(float4*)&Ws[nb][wrow][wcol]     = w0;
            *(float4*)&Ws[nb][wrow + 8][wcol] = w1;
            __syncthreads();
            buf = nb;
        }
    }

    // Epilogue: bias + store
    float bc[8];
#pragma unroll
    for (int j = 0; j < 4; j++) {
        bc[j]     = bias[bn + 4 * tx + j];
        bc[4 + j] = bias[bn + 64 + 4 * tx + j];
    }
#pragma unroll
    for (int ig = 0; ig < 2; ig++) {
#pragma unroll
        for (int i = 0; i < 4; i++) {
            int r = bm + ig * 64 + 4 * ty + i;
            int bb = r >> 11;          // batch
            int ss = r & (S_ - 1);     // seq pos
#pragma unroll
            for (int jg = 0; jg < 2; jg++) {
                int cbase = bn + jg * 64 + 4 * tx;
                float4 v;
                v.x = acc[ig * 4 + i][jg * 4 + 0] + bc[jg * 4 + 0];
                v.y = acc[ig * 4 + i][jg * 4 + 1] + bc[jg * 4 + 1];
                v.z = acc[ig * 4 + i][jg * 4 + 2] + bc[jg * 4 + 2];
                v.w = acc[ig * 4 + i][jg * 4 + 3] + bc[jg * 4 + 3];
                if (epi == 1) {
                    int h = cbase >> 7;
                    int dd = cbase & (DK_ - 1);
                    int addr = ((bb * H_ + h) * S_ + ss) * DK_ + dd;
                    *(float4*)(C + addr) = v;
                } else {
                    *(float4*)(C + r * D_ + cbase) = v;
                }
            }
        }
    }
}

// ---------------------------------------------------------------------------
// Causal flash attention, fp32. BM=BN=64, dk=128, 256 threads.
// Q/K/V tiles in dynamic smem (3 x 64 x 132 floats = 101376 B).
// P tile reuses the K buffer. Output written token-major [B,S,D].
// ---------------------------------------------------------------------------
#define FPAD 132
#define FLASH_SMEM (3 * 64 * FPAD * 4)

__global__ __launch_bounds__(256, 2) void flash_kernel(
    const float* __restrict__ Q, const float* __restrict__ K,
    const float* __restrict__ V, float* __restrict__ O)
{
    extern __shared__ float sm[];
    float* Qs = sm;                    // [64][132]
    float* Ks = sm + 64 * FPAD;        // [64][132] (doubles as P)
    float* Vs = sm + 2 * 64 * FPAD;    // [64][132]

    const int tid = threadIdx.x;
    const int tx = tid & 15, ty = tid >> 4;
    const int qblk = blockIdx.x;
    const int bh = blockIdx.y;
    const int qm0 = qblk * 64;

    const float* qb = Q + (bh * S_ + qm0) * DK_;
    const float* kb = K + bh * S_ * DK_;
    const float* vb = V + bh * S_ * DK_;

    // Load Q tile
    for (int t = tid; t < 64 * 32; t += 256) {
        int r = t >> 5, c = (t & 31) << 2;
        *(float4*)&Qs[r * FPAD + c] = *(const float4*)(qb + r * DK_ + c);
    }

    float m_i[4], l_i[4], o[4][8];
#pragma unroll
    for (int i = 0; i < 4; i++) {
        m_i[i] = -1e30f;  l_i[i] = 0.f;
#pragma unroll
        for (int j = 0; j < 8; j++) o[i][j] = 0.f;
    }

    const float scale = 0.08838834764831845f;  // 1/sqrt(128)
    const int ntiles = qblk + 1;

    for (int kn = 0; kn < ntiles; kn++) {
        __syncthreads();   // prior PV done reading Ks/Vs; also fences Q store on kn=0
        const float* kp = kb + kn * 64 * DK_;
        const float* vp = vb + kn * 64 * DK_;
        for (int t = tid; t < 64 * 32; t += 256) {
            int r = t >> 5, c = (t & 31) << 2;
            *(float4*)&Ks[r * FPAD + c] = *(const float4*)(kp + r * DK_ + c);
            *(float4*)&Vs[r * FPAD + c] = *(const float4*)(vp + r * DK_ + c);
        }
        __syncthreads();

        // S = Q K^T
        float s[4][4];
#pragma unroll
        for (int i = 0; i < 4; i++)
#pragma unroll
            for (int j = 0; j < 4; j++) s[i][j] = 0.f;

#pragma unroll 2
        for (int d = 0; d < DK_; d += 4) {
            float4 qf[4], kf[4];
#pragma unroll
            for (int i = 0; i < 4; i++)
                qf[i] = *(const float4*)&Qs[(4 * ty + i) * FPAD + d];
#pragma unroll
            for (int j = 0; j < 4; j++)
                kf[j] = *(const float4*)&Ks[(4 * tx + j) * FPAD + d];
#pragma unroll
            for (int i = 0; i < 4; i++)
#pragma unroll
                for (int j = 0; j < 4; j++)
                    s[i][j] += qf[i].x * kf[j].x + qf[i].y * kf[j].y +
                               qf[i].z * kf[j].z + qf[i].w * kf[j].w;
        }

        // scale + causal mask
        if (kn == qblk) {
#pragma unroll
            for (int i = 0; i < 4; i++)
#pragma unroll
                for (int j = 0; j < 4; j++)
                    s[i][j] = (4 * tx + j <= 4 * ty + i) ? s[i][j] * scale : -1e30f;
        } else {
#pragma unroll
            for (int i = 0; i < 4; i++)
#pragma unroll
                for (int j = 0; j < 4; j++) s[i][j] *= scale;
        }

        // Online softmax (row stats reduced across the 16 tx lanes)
#pragma unroll
        for (int i = 0; i < 4; i++) {
            float v = fmaxf(fmaxf(s[i][0], s[i][1]), fmaxf(s[i][2], s[i][3]));
            v = fmaxf(v, __shfl_xor_sync(0xffffffffu, v, 1));
            v = fmaxf(v, __shfl_xor_sync(0xffffffffu, v, 2));
            v = fmaxf(v, __shfl_xor_sync(0xffffffffu, v, 4));
            v = fmaxf(v, __shfl_xor_sync(0xffffffffu, v, 8));
            float mn = fmaxf(m_i[i], v);
            float alpha = __expf(m_i[i] - mn);
            float rs = 0.f;
#pragma unroll
            for (int j = 0; j < 4; j++) {
                float p = __expf(s[i][j] - mn);
                s[i][j] = p;
                rs += p;
            }
            rs += __shfl_xor_sync(0xffffffffu, rs, 1);
            rs += __shfl_xor_sync(0xffffffffu, rs, 2);
            rs += __shfl_xor_sync(0xffffffffu, rs, 4);
            rs += __shfl_xor_sync(0xffffffffu, rs, 8);
            l_i[i] = l_i[i] * alpha + rs;
            m_i[i] = mn;
#pragma unroll
            for (int j = 0; j < 8; j++) o[i][j] *= alpha;
        }

        __syncthreads();    // all done reading Ks before P overwrite
#pragma unroll
        for (int i = 0; i < 4; i++) {
            float4 pv = make_float4(s[i][0], s[i][1], s[i][2], s[i][3]);
            *(float4*)&Ks[(4 * ty + i) * FPAD + 4 * tx] = pv;
        }
        __syncthreads();

        // O += P V
#pragma unroll 2
        for (int kk = 0; kk < 64; kk++) {
            float p0 = Ks[(4 * ty + 0) * FPAD + kk];
            float p1 = Ks[(4 * ty + 1) * FPAD + kk];
            float p2 = Ks[(4 * ty + 2) * FPAD + kk];
            float p3 = Ks[(4 * ty + 3) * FPAD + kk];
            float4 v0 = *(const float4*)&Vs[kk * FPAD + 4 * tx];
            float4 v1 = *(const float4*)&Vs[kk * FPAD + 64 + 4 * tx];
            o[0][0] += p0 * v0.x; o[0][1] += p0 * v0.y; o[0][2] += p0 * v0.z; o[0][3] += p0 * v0.w;
            o[0][4] += p0 * v1.x; o[0][5] += p0 * v1.y; o[0][6] += p0 * v1.z; o[0][7] += p0 * v1.w;
            o[1][0] += p1 * v0.x; o[1][1] += p1 * v0.y; o[1][2] += p1 * v0.z; o[1][3] += p1 * v0.w;
            o[1][4] += p1 * v1.x; o[1][5] += p1 * v1.y; o[1][6] += p1 * v1.z; o[1][7] += p1 * v1.w;
            o[2][0] += p2 * v0.x; o[2][1] += p2 * v0.y; o[2][2] += p2 * v0.z; o[2][3] += p2 * v0.w;
            o[2][4] += p2 * v1.x; o[2][5] += p2 * v1.y; o[2][6] += p2 * v1.z; o[2][7] += p2 * v1.w;
            o[3][0] += p3 * v0.x; o[3][1] += p3 * v0.y; o[3][2] += p3 * v0.z; o[3][3] += p3 * v0.w;
            o[3][4] += p3 * v1.x; o[3][5] += p3 * v1.y; o[3][6] += p3 * v1.z; o[3][7] += p3 * v1.w;
        }
    }

    // Normalize + store token-major [B, S, D]
    const int b = bh >> 4, h = bh & 15;
    float* ob = O + (b * S_ + qm0) * D_ + h * DK_;
#pragma unroll
    for (int i = 0; i < 4; i++) {
        float inv = 1.f / l_i[i];
        int r = 4 * ty + i;
        float4 w0 = make_float4(o[i][0] * inv, o[i][1] * inv, o[i][2] * inv, o[i][3] * inv);
        float4 w1 = make_float4(o[i][4] * inv, o[i][5] * inv, o[i][6] * inv, o[i][7] * inv);
        *(float4*)(ob + r * D_ + 4 * tx) = w0;
        *(float4*)(ob + r * D_ + 64 + 4 * tx) = w1;
    }
}

// ---------------------------------------------------------------------------
// Launcher
// ---------------------------------------------------------------------------
extern "C" void kernel_launch(void* const* d_in, const int* in_sizes, int n_in,
                              void* d_out, int out_size)
{
    const float* query = (const float*)d_in[0];
    const float* key   = (const float*)d_in[1];
    const float* value = (const float*)d_in[2];
    const float* wq  = (const float*)d_in[3];
    const float* bq  = (const float*)d_in[4];
    const float* laq = (const float*)d_in[5];
    const float* lbq = (const float*)d_in[6];
    const float* wk  = (const float*)d_in[7];
    const float* bk  = (const float*)d_in[8];
    const float* lak = (const float*)d_in[9];
    const float* lbk = (const float*)d_in[10];
    const float* wv  = (const float*)d_in[11];
    const float* bv  = (const float*)d_in[12];
    const float* lav = (const float*)d_in[13];
    const float* lbv = (const float*)d_in[14];
    const float* wo  = (const float*)d_in[15];
    const float* bo  = (const float*)d_in[16];
    const float* lao = (const float*)d_in[17];
    const float* lbo = (const float*)d_in[18];

    float *effq, *effk, *effv, *effo, *gq, *gk, *gv, *gao;
    cudaGetSymbolAddress((void**)&effq, g_effw_q);
    cudaGetSymbolAddress((void**)&effk, g_effw_k);
    cudaGetSymbolAddress((void**)&effv, g_effw_v);
    cudaGetSymbolAddress((void**)&effo, g_effw_o);
    cudaGetSymbolAddress((void**)&gq, g_q);
    cudaGetSymbolAddress((void**)&gk, g_k);
    cudaGetSymbolAddress((void**)&gv, g_v);
    cudaGetSymbolAddress((void**)&gao, g_ao);

    cudaFuncSetAttribute((const void*)flash_kernel,
                         cudaFuncAttributeMaxDynamicSharedMemorySize, FLASH_SMEM);

    // 1) Effective weights
    effw_kernel<<<D_ * D_ / 256, 256>>>(wq, laq, lbq, effq);
    effw_kernel<<<D_ * D_ / 256, 256>>>(wk, lak, lbk, effk);
    effw_kernel<<<D_ * D_ / 256, 256>>>(wv, lav, lbv, effv);
    effw_kernel<<<D_ * D_ / 256, 256>>>(wo, lao, lbo, effo);

    // 2) Projections -> head-major [B,H,S,dk]
    dim3 gg(D_ / 128, BS_ / 128);  // (16, 32)
    sgemm_bias<<<gg, 256>>>(query, effq, bq, gq, 1);
    sgemm_bias<<<gg, 256>>>(key,   effk, bk, gk, 1);
    sgemm_bias<<<gg, 256>>>(value, effv, bv, gv, 1);

    // 3) Causal flash attention -> token-major [B,S,D]
    flash_kernel<<<dim3(S_ / 64, BH_), 256, FLASH_SMEM>>>(gq, gk, gv, gao);

    // 4) Output projection -> d_out
    sgemm_bias<<<gg, 256>>>(gao, effo, bo, (float*)d_out, 0);
}

// round 5
// speedup vs baseline: 1.4302x; 1.4302x over previous
#include <cuda_runtime.h>
#include <cuda_bf16.h>
#include <math.h>
#include <stdint.h>

// Problem constants
#define D_   2048
#define S_   2048
#define B_   2
#define H_   16
#define DK_  128
#define BS_  (B_*S_)   // 4096 tokens
#define BH_  (B_*H_)   // 32 head-batches

// ---------------------------------------------------------------------------
// Helpers
// ---------------------------------------------------------------------------
__device__ __forceinline__ uint32_t smem_u32(const void* p) {
    uint32_t a;
    asm("{ .reg .u64 t; cvta.to.shared.u64 t, %1; cvt.u32.u64 %0, t; }"
        : "=r"(a) : "l"(p));
    return a;
}
#define CP16(dst, src) \
    asm volatile("cp.async.cg.shared.global [%0], [%1], 16;" :: "r"(dst), "l"(src))
#define CP_COMMIT() asm volatile("cp.async.commit_group;" ::: "memory")
#define CP_WAIT(n)  asm volatile("cp.async.wait_group %0;" :: "n"(n) : "memory")

__device__ __forceinline__ void ldsm4(uint32_t* r, uint32_t addr) {
    asm volatile("ldmatrix.sync.aligned.m8n8.x4.shared.b16 {%0,%1,%2,%3}, [%4];"
        : "=r"(r[0]), "=r"(r[1]), "=r"(r[2]), "=r"(r[3]) : "r"(addr));
}
__device__ __forceinline__ void mma_bf16(float* d, const uint32_t* a, const uint32_t* b) {
    asm volatile("mma.sync.aligned.m16n8k16.row.col.f32.bf16.bf16.f32 "
        "{%0,%1,%2,%3}, {%4,%5,%6,%7}, {%8,%9}, {%0,%1,%2,%3};"
        : "+f"(d[0]), "+f"(d[1]), "+f"(d[2]), "+f"(d[3])
        : "r"(a[0]), "r"(a[1]), "r"(a[2]), "r"(a[3]), "r"(b[0]), "r"(b[1]));
}

// ---------------------------------------------------------------------------
// Device scratch (no allocations allowed)
// ---------------------------------------------------------------------------
__device__ __nv_bfloat16 g_ah[BS_*D_];
__device__ __nv_bfloat16 g_al[BS_*D_];
__device__ __nv_bfloat16 g_whq[D_*D_], g_wlq[D_*D_];
__device__ __nv_bfloat16 g_whk[D_*D_], g_wlk[D_*D_];
__device__ __nv_bfloat16 g_whv[D_*D_], g_wlv[D_*D_];
__device__ __nv_bfloat16 g_who[D_*D_], g_wlo[D_*D_];
__device__ float g_q[BH_*S_*DK_];
__device__ float g_k[BH_*S_*DK_];
__device__ float g_v[BH_*S_*DK_];
__device__ float g_ao[BS_*D_];

// ---------------------------------------------------------------------------
// Fused LoRA + transpose + bf16 split:
//   eff[k][n] = w[k][n] + la[k][:]·lb[:][n]
//   whi/wlo stored transposed: [n][k]  (K-major rows -> MMA B operand)
// ---------------------------------------------------------------------------
__global__ void wsplit_kernel(const float* __restrict__ w,
                              const float* __restrict__ la,
                              const float* __restrict__ lb,
                              __nv_bfloat16* __restrict__ whi,
                              __nv_bfloat16* __restrict__ wlo)
{
    __shared__ float t[32][33];
    const int k0 = blockIdx.y * 32, n0 = blockIdx.x * 32;
    const int x = threadIdx.x & 31, y = threadIdx.x >> 5;   // y: 0..7
#pragma unroll
    for (int i = 0; i < 4; i++) {
        int k = k0 + y + 8 * i;
        float v = w[k * D_ + n0 + x];
#pragma unroll
        for (int r = 0; r < 8; r++)
            v += la[k * 8 + r] * lb[r * D_ + n0 + x];
        t[y + 8 * i][x] = v;
    }
    __syncthreads();
#pragma unroll
    for (int i = 0; i < 4; i++) {
        int nl = y + 8 * i;
        float v = t[x][nl];
        __nv_bfloat16 h = __float2bfloat16(v);
        whi[(n0 + nl) * D_ + k0 + x] = h;
        wlo[(n0 + nl) * D_ + k0 + x] = __float2bfloat16(v - __bfloat162float(h));
    }
}

// ---------------------------------------------------------------------------
// Activation bf16 split: hi = bf16(x), lo = bf16(x - hi)
// ---------------------------------------------------------------------------
__global__ void asplit_kernel(const float* __restrict__ x,
                              __nv_bfloat16* __restrict__ hi,
                              __nv_bfloat16* __restrict__ lo)
{
    int i = (blockIdx.x * 256 + threadIdx.x) * 4;
    float4 v = *(const float4*)(x + i);
    __nv_bfloat16 h0 = __float2bfloat16(v.x);
    __nv_bfloat16 h1 = __float2bfloat16(v.y);
    __nv_bfloat16 h2 = __float2bfloat16(v.z);
    __nv_bfloat16 h3 = __float2bfloat16(v.w);
    *(__nv_bfloat162*)(hi + i)     = __nv_bfloat162(h0, h1);
    *(__nv_bfloat162*)(hi + i + 2) = __nv_bfloat162(h2, h3);
    __nv_bfloat16 l0 = __float2bfloat16(v.x - __bfloat162float(h0));
    __nv_bfloat16 l1 = __float2bfloat16(v.y - __bfloat162float(h1));
    __nv_bfloat16 l2 = __float2bfloat16(v.z - __bfloat162float(h2));
    __nv_bfloat16 l3 = __float2bfloat16(v.w - __bfloat162float(h3));
    *(__nv_bfloat162*)(lo + i)     = __nv_bfloat162(l0, l1);
    *(__nv_bfloat162*)(lo + i + 2) = __nv_bfloat162(l2, l3);
}

// ---------------------------------------------------------------------------
// bf16x3 GEMM via mma.sync (sm_80-class tensor path, works on plain sm_100):
//   C[4096][2048] = (Ah+Al) @ (Wh+Wl)^T + bias  ~=  Ah·Wh + Ah·Wl + Al·Wh
//   CTA tile 128x128, K-chunk 64, 256 threads, 8 warps (4m x 2n), warp 32x64.
//   Smem: 4 operand tiles [128][64] bf16, row stride 144 B, double-buffered.
// epi==1: scatter [B,H,S,dk]; epi==0: row-major.
// ---------------------------------------------------------------------------
#define RSTRIDE 144                       // 128 B data + 16 B pad
#define GT      (128 * RSTRIDE)           // one operand tile: 18432 B
#define GBUF    (4 * GT)                  // Ah | Al | Wh | Wl
#define GSMEM   (2 * GBUF)                // 147456 B

__global__ __launch_bounds__(256) void gemm_bf16x3(
    const __nv_bfloat16* __restrict__ Ah, const __nv_bfloat16* __restrict__ Al,
    const __nv_bfloat16* __restrict__ Wh, const __nv_bfloat16* __restrict__ Wl,
    const float* __restrict__ bias, float* __restrict__ C, int epi)
{
    extern __shared__ char dsm[];
    const uint32_t sb = smem_u32(dsm);

    const int tid  = threadIdx.x;
    const int wid  = tid >> 5;
    const int lane = tid & 31;
    const int wm   = wid >> 1;            // 0..3
    const int wn   = wid & 1;             // 0..1
    const int bm   = blockIdx.y << 7;
    const int bn   = blockIdx.x << 7;

    // cp.async mapping: 4 chunks/thread/tile, idx = j*256+tid, row=idx>>3, c16=idx&7
    const __nv_bfloat16* srcs[4] = {
        Ah + (size_t)bm * D_, Al + (size_t)bm * D_,
        Wh + (size_t)bn * D_, Wl + (size_t)bn * D_ };

    float acc[2][8][4];
#pragma unroll
    for (int i = 0; i < 2; i++)
#pragma unroll
        for (int j = 0; j < 8; j++)
#pragma unroll
            for (int q = 0; q < 4; q++) acc[i][j][q] = 0.f;

    // ldmatrix addresses
    // A frag (16x16): row = lane&15, half = lane>>4 (k +8)
    const int a_row  = lane & 15;
    const int a_half = lane >> 4;
    // B frag (x4 over 16 n-rows): row = (lane&7) + (lane&16 ? 8:0), kh = (lane>>3)&1
    const int b_row  = (lane & 7) + ((lane & 16) ? 8 : 0);
    const int b_kh   = (lane >> 3) & 1;

    auto issue_tile = [&](int c, int buf) {
        const uint32_t bb = sb + buf * GBUF;
        const int ke = c * 64;
#pragma unroll
        for (int t = 0; t < 4; t++) {
            const __nv_bfloat16* src = srcs[t] + ke;
            const uint32_t db = bb + t * GT;
#pragma unroll
            for (int j = 0; j < 4; j++) {
                int idx = j * 256 + tid;
                int row = idx >> 3, c16 = idx & 7;
                CP16(db + row * RSTRIDE + c16 * 16,
                     src + (size_t)row * D_ + c16 * 8);
            }
        }
        CP_COMMIT();
    };

    issue_tile(0, 0);

#pragma unroll 1
    for (int c = 0; c < 32; c++) {
        const int buf = c & 1;
        if (c < 31) issue_tile(c + 1, buf ^ 1);
        if (c < 31) { CP_WAIT(1); } else { CP_WAIT(0); }
        __syncthreads();

        const uint32_t bb = sb + buf * GBUF;
        const uint32_t aBase = bb + (wm * 32 + a_row) * RSTRIDE + a_half * 16;
        const uint32_t bBase = bb + 2 * GT + (wn * 64 + b_row) * RSTRIDE + b_kh * 16;

#pragma unroll
        for (int ks = 0; ks < 4; ks++) {
            const uint32_t ko = ks * 32;          // 16 bf16 = 32 B
            uint32_t ah2[2][4], al2[2][4];
#pragma unroll
            for (int mf = 0; mf < 2; mf++) {
                ldsm4(ah2[mf], aBase + mf * 16 * RSTRIDE + ko);
                ldsm4(al2[mf], aBase + GT + mf * 16 * RSTRIDE + ko);
            }
            uint32_t bh2[4][4], bl2[4][4];
#pragma unroll
            for (int ng = 0; ng < 4; ng++) {
                ldsm4(bh2[ng], bBase + ng * 16 * RSTRIDE + ko);
                ldsm4(bl2[ng], bBase + GT + ng * 16 * RSTRIDE + ko);
            }
#pragma unroll
            for (int mf = 0; mf < 2; mf++) {
#pragma unroll
                for (int ng = 0; ng < 4; ng++) {
                    mma_bf16(acc[mf][2 * ng],     ah2[mf], &bh2[ng][0]);
                    mma_bf16(acc[mf][2 * ng + 1], ah2[mf], &bh2[ng][2]);
                    mma_bf16(acc[mf][2 * ng],     ah2[mf], &bl2[ng][0]);
                    mma_bf16(acc[mf][2 * ng + 1], ah2[mf], &bl2[ng][2]);
                    mma_bf16(acc[mf][2 * ng],     al2[mf], &bh2[ng][0]);
                    mma_bf16(acc[mf][2 * ng + 1], al2[mf], &bh2[ng][2]);
                }
            }
        }
        __syncthreads();
    }

    // Epilogue: bias + store straight from fragments
    const int h = blockIdx.x;             // N-tile == one head when epi==1
#pragma unroll
    for (int mf = 0; mf < 2; mf++) {
        const int r0 = bm + wm * 32 + mf * 16 + (lane >> 2);
#pragma unroll
        for (int rr = 0; rr < 2; rr++) {
            const int g = r0 + rr * 8;
            float* dst;
            if (epi == 1) {
                int b = g >> 11, s = g & (S_ - 1);
                dst = C + ((size_t)((b * H_ + h) * S_ + s)) * DK_;
            } else {
                dst = C + (size_t)g * D_ + bn;
            }
#pragma unroll
            for (int nf = 0; nf < 8; nf++) {
                const int col = wn * 64 + nf * 8 + 2 * (lane & 3);
                float2 v;
                v.x = acc[mf][nf][2 * rr + 0] + bias[bn + col];
                v.y = acc[mf][nf][2 * rr + 1] + bias[bn + col + 1];
                *(float2*)(dst + col) = v;
            }
        }
    }
}

// ---------------------------------------------------------------------------
// Causal flash attention, fp32. BM=BN=64, dk=128, 256 threads. (unchanged)
// ---------------------------------------------------------------------------
#define FPAD 132
#define FLASH_SMEM (3 * 64 * FPAD * 4)

__global__ __launch_bounds__(256, 2) void flash_kernel(
    const float* __restrict__ Q, const float* __restrict__ K,
    const float* __restrict__ V, float* __restrict__ O)
{
    extern __shared__ float sm[];
    float* Qs = sm;
    float* Ks = sm + 64 * FPAD;
    float* Vs = sm + 2 * 64 * FPAD;

    const int tid = threadIdx.x;
    const int tx = tid & 15, ty = tid >> 4;
    const int qblk = blockIdx.x;
    const int bh = blockIdx.y;
    const int qm0 = qblk * 64;

    const float* qb = Q + (bh * S_ + qm0) * DK_;
    const float* kb = K + bh * S_ * DK_;
    const float* vb = V + bh * S_ * DK_;

    for (int t = tid; t < 64 * 32; t += 256) {
        int r = t >> 5, c = (t & 31) << 2;
        *(float4*)&Qs[r * FPAD + c] = *(const float4*)(qb + r * DK_ + c);
    }

    float m_i[4], l_i[4], o[4][8];
#pragma unroll
    for (int i = 0; i < 4; i++) {
        m_i[i] = -1e30f;  l_i[i] = 0.f;
#pragma unroll
        for (int j = 0; j < 8; j++) o[i][j] = 0.f;
    }

    const float scale = 0.08838834764831845f;
    const int ntiles = qblk + 1;

    for (int kn = 0; kn < ntiles; kn++) {
        __syncthreads();
        const float* kp = kb + kn * 64 * DK_;
        const float* vp = vb + kn * 64 * DK_;
        for (int t = tid; t < 64 * 32; t += 256) {
            int r = t >> 5, c = (t & 31) << 2;
            *(float4*)&Ks[r * FPAD + c] = *(const float4*)(kp + r * DK_ + c);
            *(float4*)&Vs[r * FPAD + c] = *(const float4*)(vp + r * DK_ + c);
        }
        __syncthreads();

        float s[4][4];
#pragma unroll
        for (int i = 0; i < 4; i++)
#pragma unroll
            for (int j = 0; j < 4; j++) s[i][j] = 0.f;

#pragma unroll 2
        for (int d = 0; d < DK_; d += 4) {
            float4 qf[4], kf[4];
#pragma unroll
            for (int i = 0; i < 4; i++)
                qf[i] = *(const float4*)&Qs[(4 * ty + i) * FPAD + d];
#pragma unroll
            for (int j = 0; j < 4; j++)
                kf[j] = *(const float4*)&Ks[(4 * tx + j) * FPAD + d];
#pragma unroll
            for (int i = 0; i < 4; i++)
#pragma unroll
                for (int j = 0; j < 4; j++)
                    s[i][j] += qf[i].x * kf[j].x + qf[i].y * kf[j].y +
                               qf[i].z * kf[j].z + qf[i].w * kf[j].w;
        }

        if (kn == qblk) {
#pragma unroll
            for (int i = 0; i < 4; i++)
#pragma unroll
                for (int j = 0; j < 4; j++)
                    s[i][j] = (4 * tx + j <= 4 * ty + i) ? s[i][j] * scale : -1e30f;
        } else {
#pragma unroll
            for (int i = 0; i < 4; i++)
#pragma unroll
                for (int j = 0; j < 4; j++) s[i][j] *= scale;
        }

#pragma unroll
        for (int i = 0; i < 4; i++) {
            float v = fmaxf(fmaxf(s[i][0], s[i][1]), fmaxf(s[i][2], s[i][3]));
            v = fmaxf(v, __shfl_xor_sync(0xffffffffu, v, 1));
            v = fmaxf(v, __shfl_xor_sync(0xffffffffu, v, 2));
            v = fmaxf(v, __shfl_xor_sync(0xffffffffu, v, 4));
            v = fmaxf(v, __shfl_xor_sync(0xffffffffu, v, 8));
            float mn = fmaxf(m_i[i], v);
            float alpha = __expf(m_i[i] - mn);
            float rs = 0.f;
#pragma unroll
            for (int j = 0; j < 4; j++) {
                float p = __expf(s[i][j] - mn);
                s[i][j] = p;
                rs += p;
            }
            rs += __shfl_xor_sync(0xffffffffu, rs, 1);
            rs += __shfl_xor_sync(0xffffffffu, rs, 2);
            rs += __shfl_xor_sync(0xffffffffu, rs, 4);
            rs += __shfl_xor_sync(0xffffffffu, rs, 8);
            l_i[i] = l_i[i] * alpha + rs;
            m_i[i] = mn;
#pragma unroll
            for (int j = 0; j < 8; j++) o[i][j] *= alpha;
        }

        __syncthreads();
#pragma unroll
        for (int i = 0; i < 4; i++) {
            float4 pv = make_float4(s[i][0], s[i][1], s[i][2], s[i][3]);
            *(float4*)&Ks[(4 * ty + i) * FPAD + 4 * tx] = pv;
        }
        __syncthreads();

#pragma unroll 2
        for (int kk = 0; kk < 64; kk++) {
            float p0 = Ks[(4 * ty + 0) * FPAD + kk];
            float p1 = Ks[(4 * ty + 1) * FPAD + kk];
            float p2 = Ks[(4 * ty + 2) * FPAD + kk];
            float p3 = Ks[(4 * ty + 3) * FPAD + kk];
            float4 v0 = *(const float4*)&Vs[kk * FPAD + 4 * tx];
            float4 v1 = *(const float4*)&Vs[kk * FPAD + 64 + 4 * tx];
            o[0][0] += p0 * v0.x; o[0][1] += p0 * v0.y; o[0][2] += p0 * v0.z; o[0][3] += p0 * v0.w;
            o[0][4] += p0 * v1.x; o[0][5] += p0 * v1.y; o[0][6] += p0 * v1.z; o[0][7] += p0 * v1.w;
            o[1][0] += p1 * v0.x; o[1][1] += p1 * v0.y; o[1][2] += p1 * v0.z; o[1][3] += p1 * v0.w;
            o[1][4] += p1 * v1.x; o[1][5] += p1 * v1.y; o[1][6] += p1 * v1.z; o[1][7] += p1 * v1.w;
            o[2][0] += p2 * v0.x; o[2][1] += p2 * v0.y; o[2][2] += p2 * v0.z; o[2][3] += p2 * v0.w;
            o[2][4] += p2 * v1.x; o[2][5] += p2 * v1.y; o[2][6] += p2 * v1.z; o[2][7] += p2 * v1.w;
            o[3][0] += p3 * v0.x; o[3][1] += p3 * v0.y; o[3][2] += p3 * v0.z; o[3][3] += p3 * v0.w;
            o[3][4] += p3 * v1.x; o[3][5] += p3 * v1.y; o[3][6] += p3 * v1.z; o[3][7] += p3 * v1.w;
        }
    }

    const int b = bh >> 4, h = bh & 15;
    float* ob = O + (b * S_ + qm0) * D_ + h * DK_;
#pragma unroll
    for (int i = 0; i < 4; i++) {
        float inv = 1.f / l_i[i];
        int r = 4 * ty + i;
        float4 w0 = make_float4(o[i][0] * inv, o[i][1] * inv, o[i][2] * inv, o[i][3] * inv);
        float4 w1 = make_float4(o[i][4] * inv, o[i][5] * inv, o[i][6] * inv, o[i][7] * inv);
        *(float4*)(ob + r * D_ + 4 * tx) = w0;
        *(float4*)(ob + r * D_ + 64 + 4 * tx) = w1;
    }
}

// ---------------------------------------------------------------------------
// Launcher
// ---------------------------------------------------------------------------
extern "C" void kernel_launch(void* const* d_in, const int* in_sizes, int n_in,
                              void* d_out, int out_size)
{
    const float* query = (const float*)d_in[0];
    const float* key   = (const float*)d_in[1];
    const float* value = (const float*)d_in[2];
    const float* wq  = (const float*)d_in[3];
    const float* bq  = (const float*)d_in[4];
    const float* laq = (const float*)d_in[5];
    const float* lbq = (const float*)d_in[6];
    const float* wk  = (const float*)d_in[7];
    const float* bk  = (const float*)d_in[8];
    const float* lak = (const float*)d_in[9];
    const float* lbk = (const float*)d_in[10];
    const float* wv  = (const float*)d_in[11];
    const float* bv  = (const float*)d_in[12];
    const float* lav = (const float*)d_in[13];
    const float* lbv = (const float*)d_in[14];
    const float* wo  = (const float*)d_in[15];
    const float* bo  = (const float*)d_in[16];
    const float* lao = (const float*)d_in[17];
    const float* lbo = (const float*)d_in[18];

    __nv_bfloat16 *ah, *al, *whq, *wlq, *whk, *wlk, *whv, *wlv, *who, *wlo_;
    float *gq, *gk, *gv, *gao;
    cudaGetSymbolAddress((void**)&ah,  g_ah);
    cudaGetSymbolAddress((void**)&al,  g_al);
    cudaGetSymbolAddress((void**)&whq, g_whq);
    cudaGetSymbolAddress((void**)&wlq, g_wlq);
    cudaGetSymbolAddress((void**)&whk, g_whk);
    cudaGetSymbolAddress((void**)&wlk, g_wlk);
    cudaGetSymbolAddress((void**)&whv, g_whv);
    cudaGetSymbolAddress((void**)&wlv, g_wlv);
    cudaGetSymbolAddress((void**)&who, g_who);
    cudaGetSymbolAddress((void**)&wlo_, g_wlo);
    cudaGetSymbolAddress((void**)&gq, g_q);
    cudaGetSymbolAddress((void**)&gk, g_k);
    cudaGetSymbolAddress((void**)&gv, g_v);
    cudaGetSymbolAddress((void**)&gao, g_ao);

    cudaFuncSetAttribute((const void*)flash_kernel,
                         cudaFuncAttributeMaxDynamicSharedMemorySize, FLASH_SMEM);
    cudaFuncSetAttribute((const void*)gemm_bf16x3,
                         cudaFuncAttributeMaxDynamicSharedMemorySize, GSMEM);

    dim3 wsg(D_ / 32, D_ / 32);      // (64, 64)
    dim3 gg(D_ / 128, BS_ / 128);    // (16, 32)
    const int asg = BS_ * D_ / 1024; // 8192

    // 1) Fused LoRA + transpose + split of the four weight matrices
    wsplit_kernel<<<wsg, 256>>>(wq, laq, lbq, whq, wlq);
    wsplit_kernel<<<wsg, 256>>>(wk, lak, lbk, whk, wlk);
    wsplit_kernel<<<wsg, 256>>>(wv, lav, lbv, whv, wlv);
    wsplit_kernel<<<wsg, 256>>>(wo, lao, lbo, who, wlo_);

    // 2) Projections (split activation, then mma.sync bf16x3 GEMM)
    asplit_kernel<<<asg, 256>>>(query, ah, al);
    gemm_bf16x3<<<gg, 256, GSMEM>>>(ah, al, whq, wlq, bq, gq, 1);
    asplit_kernel<<<asg, 256>>>(key, ah, al);
    gemm_bf16x3<<<gg, 256, GSMEM>>>(ah, al, whk, wlk, bk, gk, 1);
    asplit_kernel<<<asg, 256>>>(value, ah, al);
    gemm_bf16x3<<<gg, 256, GSMEM>>>(ah, al, whv, wlv, bv, gv, 1);

    // 3) Causal flash attention -> token-major [B,S,D]
    flash_kernel<<<dim3(S_ / 64, BH_), 256, FLASH_SMEM>>>(gq, gk, gv, gao);

    // 4) Output projection -> d_out
    asplit_kernel<<<asg, 256>>>(gao, ah, al);
    gemm_bf16x3<<<gg, 256, GSMEM>>>(ah, al, who, wlo_, bo, (float*)d_out, 0);
}

// round 7
// speedup vs baseline: 2.6993x; 1.8874x over previous
#include <cuda_runtime.h>
#include <cuda_bf16.h>
#include <math.h>
#include <stdint.h>

// Problem constants
#define D_   2048
#define S_   2048
#define B_   2
#define H_   16
#define DK_  128
#define BS_  (B_*S_)   // 4096 tokens
#define BH_  (B_*H_)   // 32 head-batches

// ---------------------------------------------------------------------------
// Helpers
// ---------------------------------------------------------------------------
__device__ __forceinline__ uint32_t smem_u32(const void* p) {
    uint32_t a;
    asm("{ .reg .u64 t; cvta.to.shared.u64 t, %1; cvt.u32.u64 %0, t; }"
        : "=r"(a) : "l"(p));
    return a;
}
#define CP16(dst, src) \
    asm volatile("cp.async.cg.shared.global [%0], [%1], 16;" :: "r"(dst), "l"(src))
#define CP_COMMIT() asm volatile("cp.async.commit_group;" ::: "memory")
#define CP_WAIT(n)  asm volatile("cp.async.wait_group %0;" :: "n"(n) : "memory")

__device__ __forceinline__ void ldsm4(uint32_t* r, uint32_t addr) {
    asm volatile("ldmatrix.sync.aligned.m8n8.x4.shared.b16 {%0,%1,%2,%3}, [%4];"
        : "=r"(r[0]), "=r"(r[1]), "=r"(r[2]), "=r"(r[3]) : "r"(addr));
}
__device__ __forceinline__ void ldsm4t(uint32_t* r, uint32_t addr) {
    asm volatile("ldmatrix.sync.aligned.m8n8.x4.trans.shared.b16 {%0,%1,%2,%3}, [%4];"
        : "=r"(r[0]), "=r"(r[1]), "=r"(r[2]), "=r"(r[3]) : "r"(addr));
}
__device__ __forceinline__ void mma_bf16(float* d, const uint32_t* a, const uint32_t* b) {
    asm volatile("mma.sync.aligned.m16n8k16.row.col.f32.bf16.bf16.f32 "
        "{%0,%1,%2,%3}, {%4,%5,%6,%7}, {%8,%9}, {%0,%1,%2,%3};"
        : "+f"(d[0]), "+f"(d[1]), "+f"(d[2]), "+f"(d[3])
        : "r"(a[0]), "r"(a[1]), "r"(a[2]), "r"(a[3]), "r"(b[0]), "r"(b[1]));
}

// ---------------------------------------------------------------------------
// Device scratch (no allocations allowed)
// ---------------------------------------------------------------------------
__device__ __nv_bfloat16 g_ah[BS_*D_];
__device__ __nv_bfloat16 g_al[BS_*D_];
__device__ __nv_bfloat16 g_whq[D_*D_], g_wlq[D_*D_];
__device__ __nv_bfloat16 g_whk[D_*D_], g_wlk[D_*D_];
__device__ __nv_bfloat16 g_whv[D_*D_], g_wlv[D_*D_];
__device__ __nv_bfloat16 g_who[D_*D_], g_wlo[D_*D_];
__device__ __nv_bfloat16 g_qh[BH_*S_*DK_], g_ql[BH_*S_*DK_];
__device__ __nv_bfloat16 g_kh[BH_*S_*DK_], g_kl[BH_*S_*DK_];
__device__ __nv_bfloat16 g_vh[BH_*S_*DK_], g_vl[BH_*S_*DK_];

// ---------------------------------------------------------------------------
// Fused LoRA + transpose + bf16 split (weights)
// ---------------------------------------------------------------------------
__global__ void wsplit_kernel(const float* __restrict__ w,
                              const float* __restrict__ la,
                              const float* __restrict__ lb,
                              __nv_bfloat16* __restrict__ whi,
                              __nv_bfloat16* __restrict__ wlo)
{
    __shared__ float t[32][33];
    const int k0 = blockIdx.y * 32, n0 = blockIdx.x * 32;
    const int x = threadIdx.x & 31, y = threadIdx.x >> 5;
#pragma unroll
    for (int i = 0; i < 4; i++) {
        int k = k0 + y + 8 * i;
        float v = w[k * D_ + n0 + x];
#pragma unroll
        for (int r = 0; r < 8; r++)
            v += la[k * 8 + r] * lb[r * D_ + n0 + x];
        t[y + 8 * i][x] = v;
    }
    __syncthreads();
#pragma unroll
    for (int i = 0; i < 4; i++) {
        int nl = y + 8 * i;
        float v = t[x][nl];
        __nv_bfloat16 h = __float2bfloat16(v);
        whi[(n0 + nl) * D_ + k0 + x] = h;
        wlo[(n0 + nl) * D_ + k0 + x] = __float2bfloat16(v - __bfloat162float(h));
    }
}

// ---------------------------------------------------------------------------
// Activation bf16 split
// ---------------------------------------------------------------------------
__global__ void asplit_kernel(const float* __restrict__ x,
                              __nv_bfloat16* __restrict__ hi,
                              __nv_bfloat16* __restrict__ lo)
{
    int i = (blockIdx.x * 256 + threadIdx.x) * 4;
    float4 v = *(const float4*)(x + i);
    __nv_bfloat16 h0 = __float2bfloat16(v.x);
    __nv_bfloat16 h1 = __float2bfloat16(v.y);
    __nv_bfloat16 h2 = __float2bfloat16(v.z);
    __nv_bfloat16 h3 = __float2bfloat16(v.w);
    *(__nv_bfloat162*)(hi + i)     = __nv_bfloat162(h0, h1);
    *(__nv_bfloat162*)(hi + i + 2) = __nv_bfloat162(h2, h3);
    __nv_bfloat16 l0 = __float2bfloat16(v.x - __bfloat162float(h0));
    __nv_bfloat16 l1 = __float2bfloat16(v.y - __bfloat162float(h1));
    __nv_bfloat16 l2 = __float2bfloat16(v.z - __bfloat162float(h2));
    __nv_bfloat16 l3 = __float2bfloat16(v.w - __bfloat162float(h3));
    *(__nv_bfloat162*)(lo + i)     = __nv_bfloat162(l0, l1);
    *(__nv_bfloat162*)(lo + i + 2) = __nv_bfloat162(l2, l3);
}

// ---------------------------------------------------------------------------
// bf16x3 GEMM via mma.sync. epi==1: bf16 hi/lo head-major; epi==0: fp32.
// ---------------------------------------------------------------------------
#define RSTRIDE 144
#define GT      (128 * RSTRIDE)
#define GBUF    (4 * GT)
#define GSMEM   (2 * GBUF)

__global__ __launch_bounds__(256) void gemm_bf16x3(
    const __nv_bfloat16* __restrict__ Ah, const __nv_bfloat16* __restrict__ Al,
    const __nv_bfloat16* __restrict__ Wh, const __nv_bfloat16* __restrict__ Wl,
    const float* __restrict__ bias, float* __restrict__ C,
    __nv_bfloat16* __restrict__ Chi, __nv_bfloat16* __restrict__ Clo, int epi)
{
    extern __shared__ char dsm[];
    const uint32_t sb = smem_u32(dsm);

    const int tid  = threadIdx.x;
    const int wid  = tid >> 5;
    const int lane = tid & 31;
    const int wm   = wid >> 1;
    const int wn   = wid & 1;
    const int bm   = blockIdx.y << 7;
    const int bn   = blockIdx.x << 7;

    const __nv_bfloat16* srcs[4] = {
        Ah + (size_t)bm * D_, Al + (size_t)bm * D_,
        Wh + (size_t)bn * D_, Wl + (size_t)bn * D_ };

    float acc[2][8][4];
#pragma unroll
    for (int i = 0; i < 2; i++)
#pragma unroll
        for (int j = 0; j < 8; j++)
#pragma unroll
            for (int q = 0; q < 4; q++) acc[i][j][q] = 0.f;

    const int a_row  = lane & 15;
    const int a_half = lane >> 4;
    const int b_row  = (lane & 7) + ((lane & 16) ? 8 : 0);
    const int b_kh   = (lane >> 3) & 1;

    auto issue_tile = [&](int c, int buf) {
        const uint32_t bb = sb + buf * GBUF;
        const int ke = c * 64;
#pragma unroll
        for (int t = 0; t < 4; t++) {
            const __nv_bfloat16* src = srcs[t] + ke;
            const uint32_t db = bb + t * GT;
#pragma unroll
            for (int j = 0; j < 4; j++) {
                int idx = j * 256 + tid;
                int row = idx >> 3, c16 = idx & 7;
                CP16(db + row * RSTRIDE + c16 * 16,
                     src + (size_t)row * D_ + c16 * 8);
            }
        }
        CP_COMMIT();
    };

    issue_tile(0, 0);

#pragma unroll 1
    for (int c = 0; c < 32; c++) {
        const int buf = c & 1;
        if (c < 31) issue_tile(c + 1, buf ^ 1);
        if (c < 31) { CP_WAIT(1); } else { CP_WAIT(0); }
        __syncthreads();

        const uint32_t bb = sb + buf * GBUF;
        const uint32_t aBase = bb + (wm * 32 + a_row) * RSTRIDE + a_half * 16;
        const uint32_t bBase = bb + 2 * GT + (wn * 64 + b_row) * RSTRIDE + b_kh * 16;

#pragma unroll
        for (int ks = 0; ks < 4; ks++) {
            const uint32_t ko = ks * 32;
            uint32_t ah2[2][4], al2[2][4];
#pragma unroll
            for (int mf = 0; mf < 2; mf++) {
                ldsm4(ah2[mf], aBase + mf * 16 * RSTRIDE + ko);
                ldsm4(al2[mf], aBase + GT + mf * 16 * RSTRIDE + ko);
            }
            uint32_t bh2[4][4], bl2[4][4];
#pragma unroll
            for (int ng = 0; ng < 4; ng++) {
                ldsm4(bh2[ng], bBase + ng * 16 * RSTRIDE + ko);
                ldsm4(bl2[ng], bBase + GT + ng * 16 * RSTRIDE + ko);
            }
#pragma unroll
            for (int mf = 0; mf < 2; mf++) {
#pragma unroll
                for (int ng = 0; ng < 4; ng++) {
                    mma_bf16(acc[mf][2 * ng],     ah2[mf], &bh2[ng][0]);
                    mma_bf16(acc[mf][2 * ng + 1], ah2[mf], &bh2[ng][2]);
                    mma_bf16(acc[mf][2 * ng],     ah2[mf], &bl2[ng][0]);
                    mma_bf16(acc[mf][2 * ng + 1], ah2[mf], &bl2[ng][2]);
                    mma_bf16(acc[mf][2 * ng],     al2[mf], &bh2[ng][0]);
                    mma_bf16(acc[mf][2 * ng + 1], al2[mf], &bh2[ng][2]);
                }
            }
        }
        __syncthreads();
    }

    const int h = blockIdx.x;
#pragma unroll
    for (int mf = 0; mf < 2; mf++) {
        const int r0 = bm + wm * 32 + mf * 16 + (lane >> 2);
#pragma unroll
        for (int rr = 0; rr < 2; rr++) {
            const int g = r0 + rr * 8;
            if (epi == 1) {
                int b = g >> 11, s = g & (S_ - 1);
                size_t base = ((size_t)((b * H_ + h) * S_ + s)) * DK_;
#pragma unroll
                for (int nf = 0; nf < 8; nf++) {
                    const int col = wn * 64 + nf * 8 + 2 * (lane & 3);
                    float vx = acc[mf][nf][2 * rr + 0] + bias[bn + col];
                    float vy = acc[mf][nf][2 * rr + 1] + bias[bn + col + 1];
                    __nv_bfloat16 hx = __float2bfloat16(vx);
                    __nv_bfloat16 hy = __float2bfloat16(vy);
                    *(__nv_bfloat162*)(Chi + base + col) = __nv_bfloat162(hx, hy);
                    *(__nv_bfloat162*)(Clo + base + col) = __nv_bfloat162(
                        __float2bfloat16(vx - __bfloat162float(hx)),
                        __float2bfloat16(vy - __bfloat162float(hy)));
                }
            } else {
                float* dst = C + (size_t)g * D_ + bn;
#pragma unroll
                for (int nf = 0; nf < 8; nf++) {
                    const int col = wn * 64 + nf * 8 + 2 * (lane & 3);
                    float2 v;
                    v.x = acc[mf][nf][2 * rr + 0] + bias[bn + col];
                    v.y = acc[mf][nf][2 * rr + 1] + bias[bn + col + 1];
                    *(float2*)(dst + col) = v;
                }
            }
        }
    }
}

// ---------------------------------------------------------------------------
// Tensor-core causal flash attention, bf16x3 splits, fp32 softmax.
// BM=128 (8 warps x 16 rows), BN=64, dk=128. Rows are 256 B (128 bf16);
// smem row stride FR=272 B (16 B pad -> conflict-free ldmatrix).
// Smem: 2 Q tiles [128][272] + 2 stages x 4 KV tiles [64][272] = 208896 B.
// ---------------------------------------------------------------------------
#define FR       272
#define FQT      (128 * FR)               // 34816
#define FKT      (64 * FR)                // 17408
#define FST      (4 * FKT)                // 69632
#define FST_OFF  (2 * FQT)
#define FSMEM    (2 * FQT + 2 * FST)      // 208896

__global__ __launch_bounds__(256, 1) void flash_tc(
    const __nv_bfloat16* __restrict__ Qh, const __nv_bfloat16* __restrict__ Ql,
    const __nv_bfloat16* __restrict__ Kh, const __nv_bfloat16* __restrict__ Kl,
    const __nv_bfloat16* __restrict__ Vh, const __nv_bfloat16* __restrict__ Vl,
    __nv_bfloat16* __restrict__ Oh, __nv_bfloat16* __restrict__ Ol)
{
    extern __shared__ char dsm[];
    const uint32_t sb = smem_u32(dsm);

    const int tid  = threadIdx.x;
    const int w    = tid >> 5;
    const int lane = tid & 31;
    const int qb   = 15 - blockIdx.x;     // heavy blocks first
    const int bh   = blockIdx.y;
    const int qm0  = qb * 128;

    // ---- prologue: Q tiles (128 rows x 256 B = 16 chunks/row) ----
    {
        const __nv_bfloat16* qsrc[2] = {
            Qh + ((size_t)bh * S_ + qm0) * DK_,
            Ql + ((size_t)bh * S_ + qm0) * DK_ };
#pragma unroll
        for (int t = 0; t < 2; t++)
#pragma unroll
            for (int j = 0; j < 8; j++) {
                int idx = j * 256 + tid;
                int row = idx >> 4, c16 = idx & 15;
                CP16(sb + t * FQT + row * FR + c16 * 16,
                     qsrc[t] + (size_t)row * DK_ + c16 * 8);
            }
        CP_COMMIT();
    }
    const __nv_bfloat16* ksrc[4] = {
        Kh + (size_t)bh * S_ * DK_, Kl + (size_t)bh * S_ * DK_,
        Vh + (size_t)bh * S_ * DK_, Vl + (size_t)bh * S_ * DK_ };

    auto issue_kv = [&](int kn, int buf) {
        const uint32_t bb = sb + FST_OFF + buf * FST;
        const int ke = kn * 64;
#pragma unroll
        for (int t = 0; t < 4; t++) {
            const __nv_bfloat16* src = ksrc[t] + (size_t)ke * DK_;
            const uint32_t db = bb + t * FKT;
#pragma unroll
            for (int j = 0; j < 4; j++) {
                int idx = j * 256 + tid;
                int row = idx >> 4, c16 = idx & 15;
                CP16(db + row * FR + c16 * 16,
                     src + (size_t)row * DK_ + c16 * 8);
            }
        }
        CP_COMMIT();
    };
    issue_kv(0, 0);

    float oacc[16][4];
#pragma unroll
    for (int i = 0; i < 16; i++)
#pragma unroll
        for (int q = 0; q < 4; q++) oacc[i][q] = 0.f;
    float m_i[2] = {-1e30f, -1e30f};
    float l_i[2] = {0.f, 0.f};

    const float scale = 0.08838834764831845f;   // 1/sqrt(128)
    const int ntiles = 2 * qb + 2;
    const int grp = lane >> 2, tig = lane & 3;

    const int a_row  = lane & 15, a_half = lane >> 4;
    const int b_row  = (lane & 7) + ((lane & 16) ? 8 : 0);
    const int b_kh   = (lane >> 3) & 1;
    const int vt_row = (lane & 7) + 8 * ((lane >> 3) & 1);
    const int vt_nb  = 16 * (lane >> 4);

#pragma unroll 1
    for (int kn = 0; kn < ntiles; kn++) {
        const int buf = kn & 1;
        if (kn + 1 < ntiles) issue_kv(kn + 1, buf ^ 1);
        if (kn + 1 < ntiles) { CP_WAIT(1); } else { CP_WAIT(0); }
        __syncthreads();

        const uint32_t st = sb + FST_OFF + buf * FST;

        // ---- S = Qh·Kh + Qh·Kl + Ql·Kh  (128x64, fp32 acc) ----
        float sacc[8][4];
#pragma unroll
        for (int i = 0; i < 8; i++)
#pragma unroll
            for (int q = 0; q < 4; q++) sacc[i][q] = 0.f;

        const uint32_t qBase = sb + (16 * w + a_row) * FR + a_half * 16;
        const uint32_t kBase = st + b_row * FR + b_kh * 16;

#pragma unroll
        for (int ks = 0; ks < 8; ks++) {
            const uint32_t ko = ks * 32;
            uint32_t qhf[4], qlf[4];
            ldsm4(qhf, qBase + ko);
            ldsm4(qlf, qBase + FQT + ko);
            uint32_t kh2[4][4], kl2[4][4];
#pragma unroll
            for (int ng = 0; ng < 4; ng++) {
                ldsm4(kh2[ng], kBase + ng * 16 * FR + ko);
                ldsm4(kl2[ng], kBase + FKT + ng * 16 * FR + ko);
            }
#pragma unroll
            for (int ng = 0; ng < 4; ng++) {
                mma_bf16(sacc[2 * ng],     qhf, &kh2[ng][0]);
                mma_bf16(sacc[2 * ng + 1], qhf, &kh2[ng][2]);
                mma_bf16(sacc[2 * ng],     qhf, &kl2[ng][0]);
                mma_bf16(sacc[2 * ng + 1], qhf, &kl2[ng][2]);
                mma_bf16(sacc[2 * ng],     qlf, &kh2[ng][0]);
                mma_bf16(sacc[2 * ng + 1], qlf, &kh2[ng][2]);
            }
        }

        // ---- scale + causal mask ----
        const int r0 = qm0 + 16 * w + grp;
        const int r1 = r0 + 8;
        const bool boundary = (kn >= 2 * qb);
#pragma unroll
        for (int nf = 0; nf < 8; nf++) {
            const int c0 = kn * 64 + nf * 8 + 2 * tig;
            if (boundary) {
                sacc[nf][0] = (c0     <= r0) ? sacc[nf][0] * scale : -1e30f;
                sacc[nf][1] = (c0 + 1 <= r0) ? sacc[nf][1] * scale : -1e30f;
                sacc[nf][2] = (c0     <= r1) ? sacc[nf][2] * scale : -1e30f;
                sacc[nf][3] = (c0 + 1 <= r1) ? sacc[nf][3] * scale : -1e30f;
            } else {
                sacc[nf][0] *= scale; sacc[nf][1] *= scale;
                sacc[nf][2] *= scale; sacc[nf][3] *= scale;
            }
        }

        // ---- online softmax (per row-half; stats across 4 lanes) ----
#pragma unroll
        for (int hh = 0; hh < 2; hh++) {
            float mx = -1e30f;
#pragma unroll
            for (int nf = 0; nf < 8; nf++)
                mx = fmaxf(mx, fmaxf(sacc[nf][2 * hh], sacc[nf][2 * hh + 1]));
            mx = fmaxf(mx, __shfl_xor_sync(0xffffffffu, mx, 1));
            mx = fmaxf(mx, __shfl_xor_sync(0xffffffffu, mx, 2));
            float mn = fmaxf(m_i[hh], mx);
            float alpha = __expf(m_i[hh] - mn);
            float rs = 0.f;
#pragma unroll
            for (int nf = 0; nf < 8; nf++) {
                float p0 = __expf(sacc[nf][2 * hh]     - mn);
                float p1 = __expf(sacc[nf][2 * hh + 1] - mn);
                sacc[nf][2 * hh] = p0; sacc[nf][2 * hh + 1] = p1;
                rs += p0 + p1;
            }
            rs += __shfl_xor_sync(0xffffffffu, rs, 1);
            rs += __shfl_xor_sync(0xffffffffu, rs, 2);
            l_i[hh] = l_i[hh] * alpha + rs;
            m_i[hh] = mn;
#pragma unroll
            for (int nf = 0; nf < 16; nf++) {
                oacc[nf][2 * hh] *= alpha; oacc[nf][2 * hh + 1] *= alpha;
            }
        }

        // ---- pack P (C-layout -> A-frag), split hi/lo ----
        // q=0 -> a0 = frag 2j cols(0,1) row grp;  q=1 -> a1 = frag 2j cols(2,3) row grp+8
        // q=2 -> a2 = frag 2j+1 cols(0,1);        q=3 -> a3 = frag 2j+1 cols(2,3)
        uint32_t ph[4][4], pl[4][4];
#pragma unroll
        for (int j = 0; j < 4; j++) {
#pragma unroll
            for (int q = 0; q < 4; q++) {
                float x0 = sacc[2 * j + (q >> 1)][(q & 1) ? 2 : 0];
                float x1 = sacc[2 * j + (q >> 1)][(q & 1) ? 3 : 1];
                __nv_bfloat16 h0 = __float2bfloat16(x0);
                __nv_bfloat16 h1 = __float2bfloat16(x1);
                __nv_bfloat162 hp = __nv_bfloat162(h0, h1);
                ph[j][q] = *(uint32_t*)&hp;
                __nv_bfloat162 lp = __nv_bfloat162(
                    __float2bfloat16(x0 - __bfloat162float(h0)),
                    __float2bfloat16(x1 - __bfloat162float(h1)));
                pl[j][q] = *(uint32_t*)&lp;
            }
        }

        // ---- O += Ph·Vh + Ph·Vl + Pl·Vh  (V via ldmatrix.trans) ----
        const uint32_t vBase = st + 2 * FKT + vt_row * FR + vt_nb;
#pragma unroll
        for (int ks = 0; ks < 4; ks++) {
            const uint32_t kro = ks * 16 * FR;
            uint32_t vh2[8][4], vl2[8][4];
#pragma unroll
            for (int vg = 0; vg < 8; vg++) {
                ldsm4t(vh2[vg], vBase + kro + vg * 32);
                ldsm4t(vl2[vg], vBase + FKT + kro + vg * 32);
            }
#pragma unroll
            for (int vg = 0; vg < 8; vg++) {
                mma_bf16(oacc[2 * vg],     ph[ks], &vh2[vg][0]);
                mma_bf16(oacc[2 * vg + 1], ph[ks], &vh2[vg][2]);
                mma_bf16(oacc[2 * vg],     ph[ks], &vl2[vg][0]);
                mma_bf16(oacc[2 * vg + 1], ph[ks], &vl2[vg][2]);
                mma_bf16(oacc[2 * vg],     pl[ks], &vh2[vg][0]);
                mma_bf16(oacc[2 * vg + 1], pl[ks], &vh2[vg][2]);
            }
        }
        __syncthreads();
    }

    // ---- epilogue: normalize, split hi/lo, store token-major [B,S,D] ----
    const int b = bh >> 4, h = bh & 15;
    const float inv0 = 1.f / l_i[0], inv1 = 1.f / l_i[1];
    const int row0 = qm0 + 16 * w + grp;
    const size_t t0 = ((size_t)b * S_ + row0) * D_;
    const size_t t1 = t0 + 8 * D_;
#pragma unroll
    for (int nf = 0; nf < 16; nf++) {
        const int col = h * DK_ + nf * 8 + 2 * tig;
        float v0 = oacc[nf][0] * inv0, v1 = oacc[nf][1] * inv0;
        float v2 = oacc[nf][2] * inv1, v3 = oacc[nf][3] * inv1;
        __nv_bfloat16 h0 = __float2bfloat16(v0), h1 = __float2bfloat16(v1);
        __nv_bfloat16 h2 = __float2bfloat16(v2), h3 = __float2bfloat16(v3);
        *(__nv_bfloat162*)(Oh + t0 + col) = __nv_bfloat162(h0, h1);
        *(__nv_bfloat162*)(Oh + t1 + col) = __nv_bfloat162(h2, h3);
        *(__nv_bfloat162*)(Ol + t0 + col) = __nv_bfloat162(
            __float2bfloat16(v0 - __bfloat162float(h0)),
            __float2bfloat16(v1 - __bfloat162float(h1)));
        *(__nv_bfloat162*)(Ol + t1 + col) = __nv_bfloat162(
            __float2bfloat16(v2 - __bfloat162float(h2)),
            __float2bfloat16(v3 - __bfloat162float(h3)));
    }
}

// ---------------------------------------------------------------------------
// Launcher
// ---------------------------------------------------------------------------
extern "C" void kernel_launch(void* const* d_in, const int* in_sizes, int n_in,
                              void* d_out, int out_size)
{
    const float* query = (const float*)d_in[0];
    const float* key   = (const float*)d_in[1];
    const float* value = (const float*)d_in[2];
    const float* wq  = (const float*)d_in[3];
    const float* bq  = (const float*)d_in[4];
    const float* laq = (const float*)d_in[5];
    const float* lbq = (const float*)d_in[6];
    const float* wk  = (const float*)d_in[7];
    const float* bk  = (const float*)d_in[8];
    const float* lak = (const float*)d_in[9];
    const float* lbk = (const float*)d_in[10];
    const float* wv  = (const float*)d_in[11];
    const float* bv  = (const float*)d_in[12];
    const float* lav = (const float*)d_in[13];
    const float* lbv = (const float*)d_in[14];
    const float* wo  = (const float*)d_in[15];
    const float* bo  = (const float*)d_in[16];
    const float* lao = (const float*)d_in[17];
    const float* lbo = (const float*)d_in[18];

    __nv_bfloat16 *ah, *al, *whq, *wlq, *whk, *wlk, *whv, *wlv, *who, *wlo_;
    __nv_bfloat16 *qh, *ql, *kh, *kl, *vh, *vl;
    cudaGetSymbolAddress((void**)&ah,  g_ah);
    cudaGetSymbolAddress((void**)&al,  g_al);
    cudaGetSymbolAddress((void**)&whq, g_whq);
    cudaGetSymbolAddress((void**)&wlq, g_wlq);
    cudaGetSymbolAddress((void**)&whk, g_whk);
    cudaGetSymbolAddress((void**)&wlk, g_wlk);
    cudaGetSymbolAddress((void**)&whv, g_whv);
    cudaGetSymbolAddress((void**)&wlv, g_wlv);
    cudaGetSymbolAddress((void**)&who, g_who);
    cudaGetSymbolAddress((void**)&wlo_, g_wlo);
    cudaGetSymbolAddress((void**)&qh, g_qh);
    cudaGetSymbolAddress((void**)&ql, g_ql);
    cudaGetSymbolAddress((void**)&kh, g_kh);
    cudaGetSymbolAddress((void**)&kl, g_kl);
    cudaGetSymbolAddress((void**)&vh, g_vh);
    cudaGetSymbolAddress((void**)&vl, g_vl);

    cudaFuncSetAttribute((const void*)gemm_bf16x3,
                         cudaFuncAttributeMaxDynamicSharedMemorySize, GSMEM);
    cudaFuncSetAttribute((const void*)flash_tc,
                         cudaFuncAttributeMaxDynamicSharedMemorySize, FSMEM);

    dim3 wsg(D_ / 32, D_ / 32);      // (64, 64)
    dim3 gg(D_ / 128, BS_ / 128);    // (16, 32)
    const int asg = BS_ * D_ / 1024; // 8192

    // 1) Weight LoRA + transpose + split
    wsplit_kernel<<<wsg, 256>>>(wq, laq, lbq, whq, wlq);
    wsplit_kernel<<<wsg, 256>>>(wk, lak, lbk, whk, wlk);
    wsplit_kernel<<<wsg, 256>>>(wv, lav, lbv, whv, wlv);
    wsplit_kernel<<<wsg, 256>>>(wo, lao, lbo, who, wlo_);

    // 2) Projections -> bf16 hi/lo, head-major
    asplit_kernel<<<asg, 256>>>(query, ah, al);
    gemm_bf16x3<<<gg, 256, GSMEM>>>(ah, al, whq, wlq, bq, nullptr, qh, ql, 1);
    asplit_kernel<<<asg, 256>>>(key, ah, al);
    gemm_bf16x3<<<gg, 256, GSMEM>>>(ah, al, whk, wlk, bk, nullptr, kh, kl, 1);
    asplit_kernel<<<asg, 256>>>(value, ah, al);
    gemm_bf16x3<<<gg, 256, GSMEM>>>(ah, al, whv, wlv, bv, nullptr, vh, vl, 1);

    // 3) Tensor-core causal flash attention -> bf16 hi/lo token-major
    flash_tc<<<dim3(16, BH_), 256, FSMEM>>>(qh, ql, kh, kl, vh, vl, ah, al);

    // 4) Output projection -> d_out (fp32)
    gemm_bf16x3<<<gg, 256, GSMEM>>>(ah, al, who, wlo_, bo, (float*)d_out,
                                    nullptr, nullptr, 0);
}

// round 8
// speedup vs baseline: 2.7023x; 1.0011x over previous
#include <cuda_runtime.h>
#include <cuda_bf16.h>
#include <math.h>
#include <stdint.h>

// Problem constants
#define D_   2048
#define S_   2048
#define B_   2
#define H_   16
#define DK_  128
#define BS_  (B_*S_)   // 4096 tokens
#define BH_  (B_*H_)   // 32 head-batches

// ---------------------------------------------------------------------------
// Helpers
// ---------------------------------------------------------------------------
__device__ __forceinline__ uint32_t smem_u32(const void* p) {
    uint32_t a;
    asm("{ .reg .u64 t; cvta.to.shared.u64 t, %1; cvt.u32.u64 %0, t; }"
        : "=r"(a) : "l"(p));
    return a;
}
#define CP16(dst, src) \
    asm volatile("cp.async.cg.shared.global [%0], [%1], 16;" :: "r"(dst), "l"(src))
#define CP_COMMIT() asm volatile("cp.async.commit_group;" ::: "memory")
#define CP_WAIT(n)  asm volatile("cp.async.wait_group %0;" :: "n"(n) : "memory")

__device__ __forceinline__ void ldsm4(uint32_t* r, uint32_t addr) {
    asm volatile("ldmatrix.sync.aligned.m8n8.x4.shared.b16 {%0,%1,%2,%3}, [%4];"
        : "=r"(r[0]), "=r"(r[1]), "=r"(r[2]), "=r"(r[3]) : "r"(addr));
}
__device__ __forceinline__ void ldsm4t(uint32_t* r, uint32_t addr) {
    asm volatile("ldmatrix.sync.aligned.m8n8.x4.trans.shared.b16 {%0,%1,%2,%3}, [%4];"
        : "=r"(r[0]), "=r"(r[1]), "=r"(r[2]), "=r"(r[3]) : "r"(addr));
}
__device__ __forceinline__ void mma_bf16(float* d, const uint32_t* a, const uint32_t* b) {
    asm volatile("mma.sync.aligned.m16n8k16.row.col.f32.bf16.bf16.f32 "
        "{%0,%1,%2,%3}, {%4,%5,%6,%7}, {%8,%9}, {%0,%1,%2,%3};"
        : "+f"(d[0]), "+f"(d[1]), "+f"(d[2]), "+f"(d[3])
        : "r"(a[0]), "r"(a[1]), "r"(a[2]), "r"(a[3]), "r"(b[0]), "r"(b[1]));
}

// ---------------------------------------------------------------------------
// Device scratch (no allocations allowed)
// ---------------------------------------------------------------------------
__device__ __nv_bfloat16 g_ah[BS_*D_];
__device__ __nv_bfloat16 g_al[BS_*D_];
__device__ __nv_bfloat16 g_whq[D_*D_], g_wlq[D_*D_];
__device__ __nv_bfloat16 g_whk[D_*D_], g_wlk[D_*D_];
__device__ __nv_bfloat16 g_whv[D_*D_], g_wlv[D_*D_];
__device__ __nv_bfloat16 g_who[D_*D_], g_wlo[D_*D_];
__device__ __nv_bfloat16 g_qh[BH_*S_*DK_], g_ql[BH_*S_*DK_];
__device__ __nv_bfloat16 g_kh[BH_*S_*DK_], g_kl[BH_*S_*DK_];
__device__ __nv_bfloat16 g_vh[BH_*S_*DK_], g_vl[BH_*S_*DK_];

// ---------------------------------------------------------------------------
// Fused LoRA + transpose + bf16 split (weights)
// ---------------------------------------------------------------------------
__global__ void wsplit_kernel(const float* __restrict__ w,
                              const float* __restrict__ la,
                              const float* __restrict__ lb,
                              __nv_bfloat16* __restrict__ whi,
                              __nv_bfloat16* __restrict__ wlo)
{
    __shared__ float t[32][33];
    const int k0 = blockIdx.y * 32, n0 = blockIdx.x * 32;
    const int x = threadIdx.x & 31, y = threadIdx.x >> 5;
#pragma unroll
    for (int i = 0; i < 4; i++) {
        int k = k0 + y + 8 * i;
        float v = w[k * D_ + n0 + x];
#pragma unroll
        for (int r = 0; r < 8; r++)
            v += la[k * 8 + r] * lb[r * D_ + n0 + x];
        t[y + 8 * i][x] = v;
    }
    __syncthreads();
#pragma unroll
    for (int i = 0; i < 4; i++) {
        int nl = y + 8 * i;
        float v = t[x][nl];
        __nv_bfloat16 h = __float2bfloat16(v);
        whi[(n0 + nl) * D_ + k0 + x] = h;
        wlo[(n0 + nl) * D_ + k0 + x] = __float2bfloat16(v - __bfloat162float(h));
    }
}

// ---------------------------------------------------------------------------
// Activation bf16 split
// ---------------------------------------------------------------------------
__global__ void asplit_kernel(const float* __restrict__ x,
                              __nv_bfloat16* __restrict__ hi,
                              __nv_bfloat16* __restrict__ lo)
{
    int i = (blockIdx.x * 256 + threadIdx.x) * 4;
    float4 v = *(const float4*)(x + i);
    __nv_bfloat16 h0 = __float2bfloat16(v.x);
    __nv_bfloat16 h1 = __float2bfloat16(v.y);
    __nv_bfloat16 h2 = __float2bfloat16(v.z);
    __nv_bfloat16 h3 = __float2bfloat16(v.w);
    *(__nv_bfloat162*)(hi + i)     = __nv_bfloat162(h0, h1);
    *(__nv_bfloat162*)(hi + i + 2) = __nv_bfloat162(h2, h3);
    __nv_bfloat16 l0 = __float2bfloat16(v.x - __bfloat162float(h0));
    __nv_bfloat16 l1 = __float2bfloat16(v.y - __bfloat162float(h1));
    __nv_bfloat16 l2 = __float2bfloat16(v.z - __bfloat162float(h2));
    __nv_bfloat16 l3 = __float2bfloat16(v.w - __bfloat162float(h3));
    *(__nv_bfloat162*)(lo + i)     = __nv_bfloat162(l0, l1);
    *(__nv_bfloat162*)(lo + i + 2) = __nv_bfloat162(l2, l3);
}

// ---------------------------------------------------------------------------
// bf16x3 GEMM via mma.sync. K-chunk 32, 2 CTAs/SM (80 KB smem).
// epi==1: bf16 hi/lo head-major; epi==0: fp32 row-major.
// ---------------------------------------------------------------------------
#define RSTRIDE 80                        // 64 B data + 16 B pad
#define GT      (128 * RSTRIDE)           // 10240
#define GBUF    (4 * GT)                  // 40960
#define GSMEM   (2 * GBUF)                // 81920

__global__ __launch_bounds__(256, 2) void gemm_bf16x3(
    const __nv_bfloat16* __restrict__ Ah, const __nv_bfloat16* __restrict__ Al,
    const __nv_bfloat16* __restrict__ Wh, const __nv_bfloat16* __restrict__ Wl,
    const float* __restrict__ bias, float* __restrict__ C,
    __nv_bfloat16* __restrict__ Chi, __nv_bfloat16* __restrict__ Clo, int epi)
{
    extern __shared__ char dsm[];
    const uint32_t sb = smem_u32(dsm);

    const int tid  = threadIdx.x;
    const int wid  = tid >> 5;
    const int lane = tid & 31;
    const int wm   = wid >> 1;
    const int wn   = wid & 1;
    const int bm   = blockIdx.y << 7;
    const int bn   = blockIdx.x << 7;

    const __nv_bfloat16* srcs[4] = {
        Ah + (size_t)bm * D_, Al + (size_t)bm * D_,
        Wh + (size_t)bn * D_, Wl + (size_t)bn * D_ };

    float acc[2][8][4];
#pragma unroll
    for (int i = 0; i < 2; i++)
#pragma unroll
        for (int j = 0; j < 8; j++)
#pragma unroll
            for (int q = 0; q < 4; q++) acc[i][j][q] = 0.f;

    const int a_row  = lane & 15;
    const int a_half = lane >> 4;
    const int b_row  = (lane & 7) + ((lane & 16) ? 8 : 0);
    const int b_kh   = (lane >> 3) & 1;

    // K-chunk 32: each tile is 128 rows x 64 B -> 2 chunks/thread/tile
    auto issue_tile = [&](int c, int buf) {
        const uint32_t bb = sb + buf * GBUF;
        const int ke = c * 32;
#pragma unroll
        for (int t = 0; t < 4; t++) {
            const __nv_bfloat16* src = srcs[t] + ke;
            const uint32_t db = bb + t * GT;
#pragma unroll
            for (int j = 0; j < 2; j++) {
                int idx = j * 256 + tid;
                int row = idx >> 2, c16 = idx & 3;
                CP16(db + row * RSTRIDE + c16 * 16,
                     src + (size_t)row * D_ + c16 * 8);
            }
        }
        CP_COMMIT();
    };

    issue_tile(0, 0);

#pragma unroll 1
    for (int c = 0; c < 64; c++) {
        const int buf = c & 1;
        if (c < 63) issue_tile(c + 1, buf ^ 1);
        if (c < 63) { CP_WAIT(1); } else { CP_WAIT(0); }
        __syncthreads();

        const uint32_t bb = sb + buf * GBUF;
        const uint32_t aBase = bb + (wm * 32 + a_row) * RSTRIDE + a_half * 16;
        const uint32_t bBase = bb + 2 * GT + (wn * 64 + b_row) * RSTRIDE + b_kh * 16;

#pragma unroll
        for (int ks = 0; ks < 2; ks++) {
            const uint32_t ko = ks * 32;
            uint32_t ah2[2][4], al2[2][4];
#pragma unroll
            for (int mf = 0; mf < 2; mf++) {
                ldsm4(ah2[mf], aBase + mf * 16 * RSTRIDE + ko);
                ldsm4(al2[mf], aBase + GT + mf * 16 * RSTRIDE + ko);
            }
            uint32_t bh2[4][4], bl2[4][4];
#pragma unroll
            for (int ng = 0; ng < 4; ng++) {
                ldsm4(bh2[ng], bBase + ng * 16 * RSTRIDE + ko);
                ldsm4(bl2[ng], bBase + GT + ng * 16 * RSTRIDE + ko);
            }
#pragma unroll
            for (int mf = 0; mf < 2; mf++) {
#pragma unroll
                for (int ng = 0; ng < 4; ng++) {
                    mma_bf16(acc[mf][2 * ng],     ah2[mf], &bh2[ng][0]);
                    mma_bf16(acc[mf][2 * ng + 1], ah2[mf], &bh2[ng][2]);
                    mma_bf16(acc[mf][2 * ng],     ah2[mf], &bl2[ng][0]);
                    mma_bf16(acc[mf][2 * ng + 1], ah2[mf], &bl2[ng][2]);
                    mma_bf16(acc[mf][2 * ng],     al2[mf], &bh2[ng][0]);
                    mma_bf16(acc[mf][2 * ng + 1], al2[mf], &bh2[ng][2]);
                }
            }
        }
        __syncthreads();
    }

    const int h = blockIdx.x;
#pragma unroll
    for (int mf = 0; mf < 2; mf++) {
        const int r0 = bm + wm * 32 + mf * 16 + (lane >> 2);
#pragma unroll
        for (int rr = 0; rr < 2; rr++) {
            const int g = r0 + rr * 8;
            if (epi == 1) {
                int b = g >> 11, s = g & (S_ - 1);
                size_t base = ((size_t)((b * H_ + h) * S_ + s)) * DK_;
#pragma unroll
                for (int nf = 0; nf < 8; nf++) {
                    const int col = wn * 64 + nf * 8 + 2 * (lane & 3);
                    float vx = acc[mf][nf][2 * rr + 0] + bias[bn + col];
                    float vy = acc[mf][nf][2 * rr + 1] + bias[bn + col + 1];
                    __nv_bfloat16 hx = __float2bfloat16(vx);
                    __nv_bfloat16 hy = __float2bfloat16(vy);
                    *(__nv_bfloat162*)(Chi + base + col) = __nv_bfloat162(hx, hy);
                    *(__nv_bfloat162*)(Clo + base + col) = __nv_bfloat162(
                        __float2bfloat16(vx - __bfloat162float(hx)),
                        __float2bfloat16(vy - __bfloat162float(hy)));
                }
            } else {
                float* dst = C + (size_t)g * D_ + bn;
#pragma unroll
                for (int nf = 0; nf < 8; nf++) {
                    const int col = wn * 64 + nf * 8 + 2 * (lane & 3);
                    float2 v;
                    v.x = acc[mf][nf][2 * rr + 0] + bias[bn + col];
                    v.y = acc[mf][nf][2 * rr + 1] + bias[bn + col + 1];
                    *(float2*)(dst + col) = v;
                }
            }
        }
    }
}

// ---------------------------------------------------------------------------
// Tensor-core causal flash attention, bf16x3 splits, fp32 softmax.
// BM=128 (8 warps x 16 rows), BN=64, dk=128, FR=272 (unchanged from R7).
// ---------------------------------------------------------------------------
#define FR       272
#define FQT      (128 * FR)               // 34816
#define FKT      (64 * FR)                // 17408
#define FST      (4 * FKT)                // 69632
#define FST_OFF  (2 * FQT)
#define FSMEM    (2 * FQT + 2 * FST)      // 208896

__global__ __launch_bounds__(256, 1) void flash_tc(
    const __nv_bfloat16* __restrict__ Qh, const __nv_bfloat16* __restrict__ Ql,
    const __nv_bfloat16* __restrict__ Kh, const __nv_bfloat16* __restrict__ Kl,
    const __nv_bfloat16* __restrict__ Vh, const __nv_bfloat16* __restrict__ Vl,
    __nv_bfloat16* __restrict__ Oh, __nv_bfloat16* __restrict__ Ol)
{
    extern __shared__ char dsm[];
    const uint32_t sb = smem_u32(dsm);

    const int tid  = threadIdx.x;
    const int w    = tid >> 5;
    const int lane = tid & 31;
    const int qb   = 15 - blockIdx.x;     // heavy blocks first
    const int bh   = blockIdx.y;
    const int qm0  = qb * 128;

    {
        const __nv_bfloat16* qsrc[2] = {
            Qh + ((size_t)bh * S_ + qm0) * DK_,
            Ql + ((size_t)bh * S_ + qm0) * DK_ };
#pragma unroll
        for (int t = 0; t < 2; t++)
#pragma unroll
            for (int j = 0; j < 8; j++) {
                int idx = j * 256 + tid;
                int row = idx >> 4, c16 = idx & 15;
                CP16(sb + t * FQT + row * FR + c16 * 16,
                     qsrc[t] + (size_t)row * DK_ + c16 * 8);
            }
        CP_COMMIT();
    }
    const __nv_bfloat16* ksrc[4] = {
        Kh + (size_t)bh * S_ * DK_, Kl + (size_t)bh * S_ * DK_,
        Vh + (size_t)bh * S_ * DK_, Vl + (size_t)bh * S_ * DK_ };

    auto issue_kv = [&](int kn, int buf) {
        const uint32_t bb = sb + FST_OFF + buf * FST;
        const int ke = kn * 64;
#pragma unroll
        for (int t = 0; t < 4; t++) {
            const __nv_bfloat16* src = ksrc[t] + (size_t)ke * DK_;
            const uint32_t db = bb + t * FKT;
#pragma unroll
            for (int j = 0; j < 4; j++) {
                int idx = j * 256 + tid;
                int row = idx >> 4, c16 = idx & 15;
                CP16(db + row * FR + c16 * 16,
                     src + (size_t)row * DK_ + c16 * 8);
            }
        }
        CP_COMMIT();
    };
    issue_kv(0, 0);

    float oacc[16][4];
#pragma unroll
    for (int i = 0; i < 16; i++)
#pragma unroll
        for (int q = 0; q < 4; q++) oacc[i][q] = 0.f;
    float m_i[2] = {-1e30f, -1e30f};
    float l_i[2] = {0.f, 0.f};

    const float scale = 0.08838834764831845f;
    const int ntiles = 2 * qb + 2;
    const int grp = lane >> 2, tig = lane & 3;

    const int a_row  = lane & 15, a_half = lane >> 4;
    const int b_row  = (lane & 7) + ((lane & 16) ? 8 : 0);
    const int b_kh   = (lane >> 3) & 1;
    const int vt_row = (lane & 7) + 8 * ((lane >> 3) & 1);
    const int vt_nb  = 16 * (lane >> 4);

#pragma unroll 1
    for (int kn = 0; kn < ntiles; kn++) {
        const int buf = kn & 1;
        if (kn + 1 < ntiles) issue_kv(kn + 1, buf ^ 1);
        if (kn + 1 < ntiles) { CP_WAIT(1); } else { CP_WAIT(0); }
        __syncthreads();

        const uint32_t st = sb + FST_OFF + buf * FST;

        float sacc[8][4];
#pragma unroll
        for (int i = 0; i < 8; i++)
#pragma unroll
            for (int q = 0; q < 4; q++) sacc[i][q] = 0.f;

        const uint32_t qBase = sb + (16 * w + a_row) * FR + a_half * 16;
        const uint32_t kBase = st + b_row * FR + b_kh * 16;

#pragma unroll
        for (int ks = 0; ks < 8; ks++) {
            const uint32_t ko = ks * 32;
            uint32_t qhf[4], qlf[4];
            ldsm4(qhf, qBase + ko);
            ldsm4(qlf, qBase + FQT + ko);
            uint32_t kh2[4][4], kl2[4][4];
#pragma unroll
            for (int ng = 0; ng < 4; ng++) {
                ldsm4(kh2[ng], kBase + ng * 16 * FR + ko);
                ldsm4(kl2[ng], kBase + FKT + ng * 16 * FR + ko);
            }
#pragma unroll
            for (int ng = 0; ng < 4; ng++) {
                mma_bf16(sacc[2 * ng],     qhf, &kh2[ng][0]);
                mma_bf16(sacc[2 * ng + 1], qhf, &kh2[ng][2]);
                mma_bf16(sacc[2 * ng],     qhf, &kl2[ng][0]);
                mma_bf16(sacc[2 * ng + 1], qhf, &kl2[ng][2]);
                mma_bf16(sacc[2 * ng],     qlf, &kh2[ng][0]);
                mma_bf16(sacc[2 * ng + 1], qlf, &kh2[ng][2]);
            }
        }

        const int r0 = qm0 + 16 * w + grp;
        const int r1 = r0 + 8;
        const bool boundary = (kn >= 2 * qb);
#pragma unroll
        for (int nf = 0; nf < 8; nf++) {
            const int c0 = kn * 64 + nf * 8 + 2 * tig;
            if (boundary) {
                sacc[nf][0] = (c0     <= r0) ? sacc[nf][0] * scale : -1e30f;
                sacc[nf][1] = (c0 + 1 <= r0) ? sacc[nf][1] * scale : -1e30f;
                sacc[nf][2] = (c0     <= r1) ? sacc[nf][2] * scale : -1e30f;
                sacc[nf][3] = (c0 + 1 <= r1) ? sacc[nf][3] * scale : -1e30f;
            } else {
                sacc[nf][0] *= scale; sacc[nf][1] *= scale;
                sacc[nf][2] *= scale; sacc[nf][3] *= scale;
            }
        }

#pragma unroll
        for (int hh = 0; hh < 2; hh++) {
            float mx = -1e30f;
#pragma unroll
            for (int nf = 0; nf < 8; nf++)
                mx = fmaxf(mx, fmaxf(sacc[nf][2 * hh], sacc[nf][2 * hh + 1]));
            mx = fmaxf(mx, __shfl_xor_sync(0xffffffffu, mx, 1));
            mx = fmaxf(mx, __shfl_xor_sync(0xffffffffu, mx, 2));
            float mn = fmaxf(m_i[hh], mx);
            float alpha = __expf(m_i[hh] - mn);
            float rs = 0.f;
#pragma unroll
            for (int nf = 0; nf < 8; nf++) {
                float p0 = __expf(sacc[nf][2 * hh]     - mn);
                float p1 = __expf(sacc[nf][2 * hh + 1] - mn);
                sacc[nf][2 * hh] = p0; sacc[nf][2 * hh + 1] = p1;
                rs += p0 + p1;
            }
            rs += __shfl_xor_sync(0xffffffffu, rs, 1);
            rs += __shfl_xor_sync(0xffffffffu, rs, 2);
            l_i[hh] = l_i[hh] * alpha + rs;
            m_i[hh] = mn;
#pragma unroll
            for (int nf = 0; nf < 16; nf++) {
                oacc[nf][2 * hh] *= alpha; oacc[nf][2 * hh + 1] *= alpha;
            }
        }

        uint32_t ph[4][4], pl[4][4];
#pragma unroll
        for (int j = 0; j < 4; j++) {
#pragma unroll
            for (int q = 0; q < 4; q++) {
                float x0 = sacc[2 * j + (q >> 1)][(q & 1) ? 2 : 0];
                float x1 = sacc[2 * j + (q >> 1)][(q & 1) ? 3 : 1];
                __nv_bfloat16 h0 = __float2bfloat16(x0);
                __nv_bfloat16 h1 = __float2bfloat16(x1);
                __nv_bfloat162 hp = __nv_bfloat162(h0, h1);
                ph[j][q] = *(uint32_t*)&hp;
                __nv_bfloat162 lp = __nv_bfloat162(
                    __float2bfloat16(x0 - __bfloat162float(h0)),
                    __float2bfloat16(x1 - __bfloat162float(h1)));
                pl[j][q] = *(uint32_t*)&lp;
            }
        }

        const uint32_t vBase = st + 2 * FKT + vt_row * FR + vt_nb;
#pragma unroll
        for (int ks = 0; ks < 4; ks++) {
            const uint32_t kro = ks * 16 * FR;
            uint32_t vh2[8][4], vl2[8][4];
#pragma unroll
            for (int vg = 0; vg < 8; vg++) {
                ldsm4t(vh2[vg], vBase + kro + vg * 32);
                ldsm4t(vl2[vg], vBase + FKT + kro + vg * 32);
            }
#pragma unroll
            for (int vg = 0; vg < 8; vg++) {
                mma_bf16(oacc[2 * vg],     ph[ks], &vh2[vg][0]);
                mma_bf16(oacc[2 * vg + 1], ph[ks], &vh2[vg][2]);
                mma_bf16(oacc[2 * vg],     ph[ks], &vl2[vg][0]);
                mma_bf16(oacc[2 * vg + 1], ph[ks], &vl2[vg][2]);
                mma_bf16(oacc[2 * vg],     pl[ks], &vh2[vg][0]);
                mma_bf16(oacc[2 * vg + 1], pl[ks], &vh2[vg][2]);
            }
        }
        __syncthreads();
    }

    const int b = bh >> 4, h = bh & 15;
    const float inv0 = 1.f / l_i[0], inv1 = 1.f / l_i[1];
    const int row0 = qm0 + 16 * w + grp;
    const size_t t0 = ((size_t)b * S_ + row0) * D_;
    const size_t t1 = t0 + 8 * D_;
#pragma unroll
    for (int nf = 0; nf < 16; nf++) {
        const int col = h * DK_ + nf * 8 + 2 * tig;
        float v0 = oacc[nf][0] * inv0, v1 = oacc[nf][1] * inv0;
        float v2 = oacc[nf][2] * inv1, v3 = oacc[nf][3] * inv1;
        __nv_bfloat16 h0 = __float2bfloat16(v0), h1 = __float2bfloat16(v1);
        __nv_bfloat16 h2 = __float2bfloat16(v2), h3 = __float2bfloat16(v3);
        *(__nv_bfloat162*)(Oh + t0 + col) = __nv_bfloat162(h0, h1);
        *(__nv_bfloat162*)(Oh + t1 + col) = __nv_bfloat162(h2, h3);
        *(__nv_bfloat162*)(Ol + t0 + col) = __nv_bfloat162(
            __float2bfloat16(v0 - __bfloat162float(h0)),
            __float2bfloat16(v1 - __bfloat162float(h1)));
        *(__nv_bfloat162*)(Ol + t1 + col) = __nv_bfloat162(
            __float2bfloat16(v2 - __bfloat162float(h2)),
            __float2bfloat16(v3 - __bfloat162float(h3)));
    }
}

// ---------------------------------------------------------------------------
// Launcher
// ---------------------------------------------------------------------------
extern "C" void kernel_launch(void* const* d_in, const int* in_sizes, int n_in,
                              void* d_out, int out_size)
{
    const float* query = (const float*)d_in[0];
    const float* key   = (const float*)d_in[1];
    const float* value = (const float*)d_in[2];
    const float* wq  = (const float*)d_in[3];
    const float* bq  = (const float*)d_in[4];
    const float* laq = (const float*)d_in[5];
    const float* lbq = (const float*)d_in[6];
    const float* wk  = (const float*)d_in[7];
    const float* bk  = (const float*)d_in[8];
    const float* lak = (const float*)d_in[9];
    const float* lbk = (const float*)d_in[10];
    const float* wv  = (const float*)d_in[11];
    const float* bv  = (const float*)d_in[12];
    const float* lav = (const float*)d_in[13];
    const float* lbv = (const float*)d_in[14];
    const float* wo  = (const float*)d_in[15];
    const float* bo  = (const float*)d_in[16];
    const float* lao = (const float*)d_in[17];
    const float* lbo = (const float*)d_in[18];

    __nv_bfloat16 *ah, *al, *whq, *wlq, *whk, *wlk, *whv, *wlv, *who, *wlo_;
    __nv_bfloat16 *qh, *ql, *kh, *kl, *vh, *vl;
    cudaGetSymbolAddress((void**)&ah,  g_ah);
    cudaGetSymbolAddress((void**)&al,  g_al);
    cudaGetSymbolAddress((void**)&whq, g_whq);
    cudaGetSymbolAddress((void**)&wlq, g_wlq);
    cudaGetSymbolAddress((void**)&whk, g_whk);
    cudaGetSymbolAddress((void**)&wlk, g_wlk);
    cudaGetSymbolAddress((void**)&whv, g_whv);
    cudaGetSymbolAddress((void**)&wlv, g_wlv);
    cudaGetSymbolAddress((void**)&who, g_who);
    cudaGetSymbolAddress((void**)&wlo_, g_wlo);
    cudaGetSymbolAddress((void**)&qh, g_qh);
    cudaGetSymbolAddress((void**)&ql, g_ql);
    cudaGetSymbolAddress((void**)&kh, g_kh);
    cudaGetSymbolAddress((void**)&kl, g_kl);
    cudaGetSymbolAddress((void**)&vh, g_vh);
    cudaGetSymbolAddress((void**)&vl, g_vl);

    cudaFuncSetAttribute((const void*)gemm_bf16x3,
                         cudaFuncAttributeMaxDynamicSharedMemorySize, GSMEM);
    cudaFuncSetAttribute((const void*)flash_tc,
                         cudaFuncAttributeMaxDynamicSharedMemorySize, FSMEM);

    dim3 wsg(D_ / 32, D_ / 32);      // (64, 64)
    dim3 gg(D_ / 128, BS_ / 128);    // (16, 32)
    const int asg = BS_ * D_ / 1024; // 8192

    // 1) Weight LoRA + transpose + split
    wsplit_kernel<<<wsg, 256>>>(wq, laq, lbq, whq, wlq);
    wsplit_kernel<<<wsg, 256>>>(wk, lak, lbk, whk, wlk);
    wsplit_kernel<<<wsg, 256>>>(wv, lav, lbv, whv, wlv);
    wsplit_kernel<<<wsg, 256>>>(wo, lao, lbo, who, wlo_);

    // 2) Projections -> bf16 hi/lo, head-major
    asplit_kernel<<<asg, 256>>>(query, ah, al);
    gemm_bf16x3<<<gg, 256, GSMEM>>>(ah, al, whq, wlq, bq, nullptr, qh, ql, 1);
    asplit_kernel<<<asg, 256>>>(key, ah, al);
    gemm_bf16x3<<<gg, 256, GSMEM>>>(ah, al, whk, wlk, bk, nullptr, kh, kl, 1);
    asplit_kernel<<<asg, 256>>>(value, ah, al);
    gemm_bf16x3<<<gg, 256, GSMEM>>>(ah, al, whv, wlv, bv, nullptr, vh, vl, 1);

    // 3) Tensor-core causal flash attention -> bf16 hi/lo token-major
    flash_tc<<<dim3(16, BH_), 256, FSMEM>>>(qh, ql, kh, kl, vh, vl, ah, al);

    // 4) Output projection -> d_out (fp32)
    gemm_bf16x3<<<gg, 256, GSMEM>>>(ah, al, who, wlo_, bo, (float*)d_out,
                                    nullptr, nullptr, 0);
}